// round 6
// baseline (speedup 1.0000x reference)
#include <cuda_runtime.h>

// Problem shape (fixed by setup_inputs): x (B=1024, S=1024, E=12), n_qubits = 12.
#define BB    1024
#define SSZ   1024
#define EE    12
#define EPSV  1e-5f
#define CHUNK 128    // s-rows per block in k2 (32 per warp)
#define BPB   8      // b-values per block in k2
#define NSTG  3      // cp.async pipeline depth (per warp)

// Scratch tables: attn[s][e], ffn[s][e]  (s in 0..1023, e in 0..11)
__device__ float g_attn[BB * EE];
__device__ float g_ffn [BB * EE];

// ---------------------------------------------------------------------------
// Kernel 1: per-row quantum "attention" and "ffn" tables (analytic collapse).
// One warp per j; 128 blocks x 256 threads.
// ---------------------------------------------------------------------------
__global__ __launch_bounds__(256) void qtb_k1(
    const float* __restrict__ x,
    const float* __restrict__ rxa,
    const float* __restrict__ rya,
    const float* __restrict__ wffn,   // (E, 12) row-major
    const float* __restrict__ bffn,
    const float* __restrict__ g1,
    const float* __restrict__ b1)
{
    __shared__ float s_attn12[12][12];            // attn rows 0..11 (for tok2)
    __shared__ __align__(16) float swx[8][148];   // per-warp x[j,0:12,0:12]
    __shared__ float scrx[12];

    const int tid  = threadIdx.x;
    const int warp = tid >> 5;
    const int lane = tid & 31;
    const int j    = blockIdx.x * 8 + warp;       // 0..1023

    if (tid < 12) scrx[tid] = __cosf(__ldg(&rxa[tid]));

    // Stage this warp's 144 contiguous floats (36 float4, coalesced)
    {
        const float4* xr = reinterpret_cast<const float4*>(x + (size_t)j * SSZ * EE);
        float4* sw = reinterpret_cast<float4*>(&swx[warp][0]);
        for (int t = lane; t < 36; t += 32) sw[t] = xr[t];
    }

    // Phase A0: attn rows 0..11 into smem (144 of 256 threads)
    if (tid < 144) {
        const int i = tid / 12;
        const int w = tid % 12;
        float z[12];
        #pragma unroll
        for (int k = 0; k < 12; k++)
            z[k] = __cosf(__ldg(&rxa[k])) * __cosf(__ldg(&x[(size_t)i * SSZ * EE + k * EE]));
        float p = 1.0f;
        if (w == 0) {
            #pragma unroll
            for (int k = 1; k < 12; k++) p *= z[k];
        } else {
            for (int k = 0; k <= w; k++) p *= z[k];
        }
        s_attn12[i][w] = p;
    }
    __syncthreads();

    // Phase A: this warp's own attn row (lane i holds z_i, shuffle products)
    float zl = 0.0f;
    if (lane < 12)
        zl = scrx[lane] * __cosf(swx[warp][lane * 12]);
    float aw = 1.0f;
    #pragma unroll
    for (int k = 0; k < 12; k++) {
        float zk = __shfl_sync(0xffffffffu, zl, k);
        bool incl = (lane == 0) ? (k >= 1) : (k <= lane);
        if (incl) aw *= zk;
    }
    if (lane < 12) g_attn[j * 12 + lane] = aw;

    // Phase B: lane i<12 computes tok2_i via the 12-wide LN of row (j,i)
    float r = 0.0f;
    if (lane < 12) {
        float v[12];
        float mu = 0.0f;
        #pragma unroll
        for (int e = 0; e < 12; e++) {
            v[e] = swx[warp][lane * 12 + e] + s_attn12[lane][e];
            mu  += v[e];
        }
        mu *= (1.0f / 12.0f);
        float var = 0.0f;
        #pragma unroll
        for (int e = 0; e < 12; e++) { float d = v[e] - mu; var += d * d; }
        var *= (1.0f / 12.0f);
        const float inv  = rsqrtf(var + EPSV);
        const float tok2 = (v[0] - mu) * inv * __ldg(&g1[0]) + __ldg(&b1[0]);
        r = fmaxf(__cosf(tok2 + __ldg(&rya[lane])), 0.0f);
    }

    // Phase C: ffn[j,e] = b_ffn[e] + sum_i r_i * w_ffn[e,i]
    float acc = (lane < 12) ? __ldg(&bffn[lane]) : 0.0f;
    #pragma unroll
    for (int i = 0; i < 12; i++) {
        float ri = __shfl_sync(0xffffffffu, r, i);
        if (lane < 12) acc = fmaf(ri, __ldg(&wffn[lane * 12 + i]), acc);
    }
    if (lane < 12) g_ffn[j * 12 + lane] = acc;
}

// ---------------------------------------------------------------------------
// Kernel 2: out[b,s,:] = LN2( LN1(x[b,s,:] + attn[s,:]) + ffn[s,:] )
// WARP-AUTONOMOUS pipeline: each warp stages its own 32 rows via cp.async into
// private smem stages and consumes them — no __syncthreads in the main loop,
// only __syncwarp. attn/ffn register-resident. Output: direct STG with .cs
// (streaming) so out doesn't evict L2-resident x.
// grid (SSZ/CHUNK, BB/BPB), 128 threads (4 warps).
// ---------------------------------------------------------------------------
__global__ __launch_bounds__(128) void qtb_k2(
    const float* __restrict__ x,
    const float* __restrict__ g1, const float* __restrict__ b1,
    const float* __restrict__ g2, const float* __restrict__ b2,
    float* __restrict__ out)
{
    // Per-warp pipeline stages: 4 warps x NSTG x 32 rows x 12 floats = 18 KB
    __shared__ __align__(16) float sx[4][NSTG][32 * 12];
    __shared__ float sG1[12], sB1[12], sG2[12], sB2[12];

    const int tid  = threadIdx.x;
    const int warp = tid >> 5;
    const int lane = tid & 31;
    const int s    = blockIdx.x * CHUNK + tid;            // this thread's row
    const int b0   = blockIdx.y * BPB;

    const float* xw = x + ((size_t)b0 * SSZ + (blockIdx.x * CHUNK + warp * 32)) * EE;
    float*       ob = out + ((size_t)b0 * SSZ + s) * EE;
    const size_t bstride = (size_t)SSZ * EE;

    if (tid < 12) {
        sG1[tid] = g1[tid]; sB1[tid] = b1[tid];
        sG2[tid] = g2[tid]; sB2[tid] = b2[tid];
    }

    // attn/ffn for this thread's row -> registers (g_* tables are L2-hot)
    float an[12], fn[12];
    {
        const float4* ap = reinterpret_cast<const float4*>(&g_attn[s * 12]);
        const float4* fp = reinterpret_cast<const float4*>(&g_ffn [s * 12]);
        float4 a0 = ap[0], a1 = ap[1], a2 = ap[2];
        float4 f0 = fp[0], f1 = fp[1], f2 = fp[2];
        an[0]=a0.x; an[1]=a0.y; an[2]=a0.z; an[3]=a0.w;
        an[4]=a1.x; an[5]=a1.y; an[6]=a1.z; an[7]=a1.w;
        an[8]=a2.x; an[9]=a2.y; an[10]=a2.z; an[11]=a2.w;
        fn[0]=f0.x; fn[1]=f0.y; fn[2]=f0.z; fn[3]=f0.w;
        fn[4]=f1.x; fn[5]=f1.y; fn[6]=f1.z; fn[7]=f1.w;
        fn[8]=f2.x; fn[9]=f2.y; fn[10]=f2.z; fn[11]=f2.w;
    }
    __syncthreads();   // sG1..sB2 visible to all warps

    // Warp-private cp.async stage: 32 rows = 1536 B = 3 float4 per lane
    auto issue_load = [&](int buf, int bi) {
        const float* src = xw + (size_t)bi * bstride;
        unsigned dst = (unsigned)__cvta_generic_to_shared(&sx[warp][buf][0]);
        #pragma unroll
        for (int k = 0; k < 3; k++) {
            asm volatile("cp.async.cg.shared.global [%0], [%1], 16;\n"
                         :: "r"(dst + (lane + 32 * k) * 16),
                            "l"(src + (lane + 32 * k) * 4));
        }
        asm volatile("cp.async.commit_group;\n");
    };

    issue_load(0, 0);
    issue_load(1, 1);

    for (int bi = 0; bi < BPB; bi++) {
        __syncwarp();   // all lanes done reading buffer (bi-1)%NSTG (iter bi-1)
        if (bi + 2 < BPB) {
            issue_load((bi + 2) % NSTG, bi + 2);
            asm volatile("cp.async.wait_group 2;\n");   // group bi complete
        } else if (bi + 1 < BPB) {
            asm volatile("cp.async.wait_group 1;\n");
        } else {
            asm volatile("cp.async.wait_group 0;\n");
        }
        __syncwarp();   // all lanes' copies for buffer bi%NSTG have landed

        // Lane owns row `lane` of the warp's buffer. LDS.128 at 48B stride:
        // banks 12l..12l+3 mod 32 tile all banks per quarter -> conflict-free.
        const float4* row = reinterpret_cast<const float4*>(&sx[warp][bi % NSTG][lane * 12]);
        float4 q0 = row[0], q1 = row[1], q2 = row[2];

        float v[12];
        v[0]=q0.x; v[1]=q0.y; v[2]=q0.z; v[3]=q0.w;
        v[4]=q1.x; v[5]=q1.y; v[6]=q1.z; v[7]=q1.w;
        v[8]=q2.x; v[9]=q2.y; v[10]=q2.z; v[11]=q2.w;

        // x + attn, LN1
        float mu = 0.0f;
        #pragma unroll
        for (int e = 0; e < 12; e++) { v[e] += an[e]; mu += v[e]; }
        mu *= (1.0f / 12.0f);
        float var = 0.0f;
        #pragma unroll
        for (int e = 0; e < 12; e++) { float d = v[e] - mu; var += d * d; }
        var *= (1.0f / 12.0f);
        const float inv = rsqrtf(var + EPSV);

        // x1 + ffn, LN2
        float u[12];
        float mu2 = 0.0f;
        #pragma unroll
        for (int e = 0; e < 12; e++) {
            u[e] = (v[e] - mu) * inv * sG1[e] + sB1[e] + fn[e];
            mu2 += u[e];
        }
        mu2 *= (1.0f / 12.0f);
        float var2 = 0.0f;
        #pragma unroll
        for (int e = 0; e < 12; e++) { float d = u[e] - mu2; var2 += d * d; }
        var2 *= (1.0f / 12.0f);
        const float inv2 = rsqrtf(var2 + EPSV);

        float4 o0, o1, o2;
        o0.x = (u[0]  - mu2) * inv2 * sG2[0]  + sB2[0];
        o0.y = (u[1]  - mu2) * inv2 * sG2[1]  + sB2[1];
        o0.z = (u[2]  - mu2) * inv2 * sG2[2]  + sB2[2];
        o0.w = (u[3]  - mu2) * inv2 * sG2[3]  + sB2[3];
        o1.x = (u[4]  - mu2) * inv2 * sG2[4]  + sB2[4];
        o1.y = (u[5]  - mu2) * inv2 * sG2[5]  + sB2[5];
        o1.z = (u[6]  - mu2) * inv2 * sG2[6]  + sB2[6];
        o1.w = (u[7]  - mu2) * inv2 * sG2[7]  + sB2[7];
        o2.x = (u[8]  - mu2) * inv2 * sG2[8]  + sB2[8];
        o2.y = (u[9]  - mu2) * inv2 * sG2[9]  + sB2[9];
        o2.z = (u[10] - mu2) * inv2 * sG2[10] + sB2[10];
        o2.w = (u[11] - mu2) * inv2 * sG2[11] + sB2[11];

        // Streaming stores: evict-first so out doesn't push x out of L2.
        float4* op = reinterpret_cast<float4*>(ob + (size_t)bi * bstride);
        __stcs(&op[0], o0);
        __stcs(&op[1], o1);
        __stcs(&op[2], o2);
    }
}

// ---------------------------------------------------------------------------
extern "C" void kernel_launch(void* const* d_in, const int* in_sizes, int n_in,
                              void* d_out, int out_size)
{
    const float* x    = (const float*)d_in[0];   // (1024, 1024, 12)
    const float* rxa  = (const float*)d_in[1];   // (12,)
    const float* rya  = (const float*)d_in[2];   // (12,)
    const float* wffn = (const float*)d_in[3];   // (12, 12)
    const float* bffn = (const float*)d_in[4];   // (12,)
    const float* g1   = (const float*)d_in[5];
    const float* b1   = (const float*)d_in[6];
    const float* g2   = (const float*)d_in[7];
    const float* b2   = (const float*)d_in[8];
    float* out = (float*)d_out;

    qtb_k1<<<BB / 8, 256>>>(x, rxa, rya, wffn, bffn, g1, b1);
    qtb_k2<<<dim3(SSZ / CHUNK, BB / BPB), 128>>>(x, g1, b1, g2, b2, out);
}